// round 11
// baseline (speedup 1.0000x reference)
#include <cuda_runtime.h>
#include <cstdint>

// Embedding gather via TMA bulk copies: out[row,:] = weight[ids[row],:]
// ids: [8192] i32, weight: [32000,1024] f32, out: [8192,1024] f32.
//
// R6: minimize residency tail. 2 rows per CTA -> 8.2KB smem -> ~28 CTAs/SM
// resident -> the whole 4096-CTA grid is ~one wave (vs R5: 6 CTAs/SM, 33KB,
// 136-CTA straggler wave). Per CTA: 2 pipelined cp.async.bulk G->S loads
// (one mbarrier each), then bulk S->G stores as each lands.

#define DIM       1024
#define ROW_BYTES (DIM * 4)   // 4096
#define ROWS      2
#define THREADS   32

__device__ __forceinline__ void mbar_init(uint32_t a, uint32_t cnt) {
    asm volatile("mbarrier.init.shared.b64 [%0], %1;" :: "r"(a), "r"(cnt) : "memory");
}
__device__ __forceinline__ void mbar_expect_tx(uint32_t a, uint32_t bytes) {
    asm volatile("mbarrier.arrive.expect_tx.shared.b64 _, [%0], %1;"
                 :: "r"(a), "r"(bytes) : "memory");
}
__device__ __forceinline__ void mbar_wait(uint32_t a, uint32_t parity) {
    uint32_t done;
    asm volatile(
        "{\n\t.reg .pred p;\n\t"
        "mbarrier.try_wait.parity.acquire.cta.shared::cta.b64 p, [%1], %2;\n\t"
        "selp.b32 %0, 1, 0, p;\n\t}"
        : "=r"(done) : "r"(a), "r"(parity) : "memory");
    if (!done) {
        asm volatile(
            "{\n\t.reg .pred P1;\n\t"
            "W_%=:\n\t"
            "mbarrier.try_wait.parity.acquire.cta.shared::cta.b64 P1, [%0], %1, 0x989680;\n\t"
            "@P1 bra.uni D_%=;\n\t"
            "bra.uni W_%=;\n\t"
            "D_%=:\n\t}"
            :: "r"(a), "r"(parity) : "memory");
    }
}
__device__ __forceinline__ void bulk_g2s(uint32_t dst_s, const void* src_g,
                                         uint32_t bytes, uint32_t mbar) {
    asm volatile(
        "cp.async.bulk.shared::cta.global.mbarrier::complete_tx::bytes "
        "[%0], [%1], %2, [%3];"
        :: "r"(dst_s), "l"(src_g), "r"(bytes), "r"(mbar) : "memory");
}
__device__ __forceinline__ void bulk_s2g(void* dst_g, uint32_t src_s, uint32_t bytes) {
    asm volatile(
        "cp.async.bulk.global.shared::cta.bulk_group [%0], [%1], %2;"
        :: "l"(dst_g), "r"(src_s), "r"(bytes) : "memory");
}

__global__ void __launch_bounds__(THREADS)
embed_tma_kernel(const int* __restrict__ ids,
                 const float* __restrict__ weight,
                 float* __restrict__ out)
{
    __shared__ alignas(128) char     buf[ROWS][ROW_BYTES];
    __shared__ alignas(8)   uint64_t mbar[ROWS];

    const int base = blockIdx.x * ROWS;

    if (threadIdx.x == 0) {
        uint32_t mb[ROWS], bf[ROWS];
#pragma unroll
        for (int s = 0; s < ROWS; s++) {
            mb[s] = (uint32_t)__cvta_generic_to_shared(&mbar[s]);
            bf[s] = (uint32_t)__cvta_generic_to_shared(&buf[s][0]);
            mbar_init(mb[s], 1);
        }
        asm volatile("fence.proxy.async.shared::cta;" ::: "memory");

        // One int2 load fetches both ids.
        const int2 id2 = *reinterpret_cast<const int2*>(ids + base);
        const int  id[ROWS] = { id2.x, id2.y };

        // Issue both gather loads back-to-back (8KB in flight per CTA).
#pragma unroll
        for (int s = 0; s < ROWS; s++) {
            mbar_expect_tx(mb[s], ROW_BYTES);
            bulk_g2s(bf[s], (const char*)weight + (size_t)id[s] * ROW_BYTES,
                     ROW_BYTES, mb[s]);
        }

        // Drain in order.
#pragma unroll
        for (int s = 0; s < ROWS; s++) {
            mbar_wait(mb[s], 0);
            bulk_s2g(out + (size_t)(base + s) * DIM, bf[s], ROW_BYTES);
        }
        asm volatile("cp.async.bulk.commit_group;" ::: "memory");
        asm volatile("cp.async.bulk.wait_group.read 0;" ::: "memory");
    }
}

extern "C" void kernel_launch(void* const* d_in, const int* in_sizes, int n_in,
                              void* d_out, int out_size)
{
    const int*   ids    = (const int*)d_in[0];
    const float* weight = (const float*)d_in[1];
    float*       out    = (float*)d_out;

    const int n_rows = in_sizes[0];        // 8192
    const int grid   = n_rows / ROWS;      // 4096

    embed_tma_kernel<<<grid, THREADS>>>(ids, weight, out);
}

// round 12
// speedup vs baseline: 1.0507x; 1.0507x over previous
#include <cuda_runtime.h>

// Embedding gather: out[row, :] = weight[ids[row], :]
// ids: [8192] int32, weight: [32000, 1024] f32, out: [8192, 1024] f32.
//
// R7: identical to the best kernel (one CTA per row, 256 threads x float4),
// except output stores are write-through (__stwt / ST.E.WT). The output is
// never re-read, so allocating dirty lines in L2 only adds a second pass
// through LTS (fill + writeback) and evicts resident weight rows. WT stores
// stream straight to DRAM and leave L2 to the weight table.

#define DIM 1024
#define VEC (DIM / 4)   // 256 float4 per row

__global__ void __launch_bounds__(256, 8)
embed_gather_kernel(const int* __restrict__ ids,
                    const float* __restrict__ weight,
                    float* __restrict__ out)
{
    const int row = blockIdx.x;
    const int id  = __ldg(ids + row);

    const float4* __restrict__ src =
        reinterpret_cast<const float4*>(weight) + (size_t)id * VEC;
    float4* __restrict__ dst =
        reinterpret_cast<float4*>(out) + (size_t)row * VEC;

    const float4 v = __ldg(src + threadIdx.x);
    __stwt(dst + threadIdx.x, v);
}

extern "C" void kernel_launch(void* const* d_in, const int* in_sizes, int n_in,
                              void* d_out, int out_size)
{
    // metadata order: input_ids (int32, 4*2048), weight (float32, 32000*1024)
    const int*   ids    = (const int*)d_in[0];
    const float* weight = (const float*)d_in[1];
    float*       out    = (float*)d_out;

    const int n_rows = in_sizes[0];   // 8192

    embed_gather_kernel<<<n_rows, 256>>>(ids, weight, out);
}